// round 9
// baseline (speedup 1.0000x reference)
#include <cuda_runtime.h>
#include <cuda_bf16.h>
#include <cstdint>

#define BB 8
#define NN 2048
#define ITERS 50

// ---- device scratch (no allocs allowed) ----
__device__ float gE[BB * 16384], gE2[BB * 16384], gS[BB * 16384];
__device__ __nv_bfloat16 gW1[BB * 16384], gW2[BB * 16384];

// ---- f32x2 helpers (prep kernels) ----
__device__ __forceinline__ unsigned long long ffma2(unsigned long long a,
                                                    unsigned long long b,
                                                    unsigned long long c) {
    unsigned long long d;
    asm("fma.rn.f32x2 %0, %1, %2, %3;" : "=l"(d) : "l"(a), "l"(b), "l"(c));
    return d;
}
__device__ __forceinline__ unsigned long long pack2(float x) {
    union { unsigned long long u; float2 f; } c; c.f = make_float2(x, x); return c.u;
}
__device__ __forceinline__ float2 unpack2(unsigned long long v) {
    union { unsigned long long u; float2 f; } c; c.u = v; return c.f;
}

// ---- HMMA m16n8k16 bf16 -> f32 ----
__device__ __forceinline__ void mma_bf16(float c[4],
                                         uint32_t a0, uint32_t a1, uint32_t a2, uint32_t a3,
                                         uint32_t b0, uint32_t b1) {
    asm volatile(
        "mma.sync.aligned.m16n8k16.row.col.f32.bf16.bf16.f32 "
        "{%0,%1,%2,%3}, {%4,%5,%6,%7}, {%8,%9}, {%0,%1,%2,%3};"
        : "+f"(c[0]), "+f"(c[1]), "+f"(c[2]), "+f"(c[3])
        : "r"(a0), "r"(a1), "r"(a2), "r"(a3), "r"(b0), "r"(b1));
}

#define LDSM4(r0, r1, r2, r3, addr) \
    asm volatile("ldmatrix.sync.aligned.m8n8.x4.shared.b16 {%0,%1,%2,%3}, [%4];" \
        : "=r"(r0), "=r"(r1), "=r"(r2), "=r"(r3) : "r"(addr))

__device__ __forceinline__ uint32_t smem_u32(const void* p) {
    uint32_t a;
    asm("{ .reg .u64 t; cvta.to.shared.u64 t, %1; cvt.u32.u64 %0, t; }" : "=r"(a) : "l"(p));
    return a;
}

__device__ __forceinline__ void split2(float x, float y, uint32_t& hi, uint32_t& lo) {
    __nv_bfloat162 h = __float22bfloat162_rn(make_float2(x, y));
    float2 hb = __bfloat1622float2(h);
    __nv_bfloat162 l = __float22bfloat162_rn(make_float2(x - hb.x, y - hb.y));
    hi = *(uint32_t*)&h;
    lo = *(uint32_t*)&l;
}

__device__ __forceinline__ void barg(int id) {
    asm volatile("bar.sync %0, %1;" :: "r"(id), "r"(256) : "memory");
}

// ============================================================================
// kE: E = (1/8192) V V^T.  grid 64 x 256.
// ============================================================================
__global__ __launch_bounds__(256, 1) void kE(const float* __restrict__ gV) {
    extern __shared__ float sm[];
    float* sVt = sm;                         // [128][132]
    const int b = blockIdx.x >> 3, r0 = (blockIdx.x & 7) * 16;
    const int t = threadIdx.x;
    for (int idx = t; idx < 16384; idx += 256) {
        int m = idx >> 7, d = idx & 127;
        sVt[d * 132 + m] = gV[b * 16384 + idx];
    }
    __syncthreads();
    const int r = r0 + (t & 15), i0 = (t >> 4) * 8;
    unsigned long long acc[4];
#pragma unroll
    for (int e = 0; e < 4; e++) acc[e] = 0ULL;
#pragma unroll 8
    for (int d = 0; d < 128; d++) {
        unsigned long long a2 = pack2(sVt[d * 132 + r]);
        const ulonglong2* pm = (const ulonglong2*)(sVt + d * 132 + i0);
        ulonglong2 m0 = pm[0], m1 = pm[1];
        acc[0] = ffma2(m0.x, a2, acc[0]);
        acc[1] = ffma2(m0.y, a2, acc[1]);
        acc[2] = ffma2(m1.x, a2, acc[2]);
        acc[3] = ffma2(m1.y, a2, acc[3]);
    }
    const float sc = 1.0f / 8192.0f;
#pragma unroll
    for (int e = 0; e < 4; e++) {
        float2 v = unpack2(acc[e]);
        gE[b * 16384 + r * 128 + i0 + 2 * e]     = sc * v.x;
        gE[b * 16384 + r * 128 + i0 + 2 * e + 1] = sc * v.y;
    }
}

// ============================================================================
// kMM1: E2 = E*E ; S = I - E + E2.   grid 128 x 256.
// ============================================================================
__global__ __launch_bounds__(256, 1) void kMM1() {
    extern __shared__ float sm[];
    float* sA = sm;                 // E slice [8][129]
    float* sB = sm + 8 * 129;       // E full [128][128]
    const int b = blockIdx.x >> 4, r0 = (blockIdx.x & 15) * 8;
    const int t = threadIdx.x;
    for (int idx = t; idx < 1024; idx += 256) {
        int row = idx >> 7, j = idx & 127;
        sA[row * 129 + j] = gE[b * 16384 + (r0 + row) * 128 + j];
    }
    for (int idx = t; idx < 4096; idx += 256)
        ((float4*)sB)[idx] = ((const float4*)(gE + b * 16384))[idx];
    __syncthreads();
    const int rl = t & 7, r = r0 + rl, i0 = (t >> 3) * 4;
    unsigned long long acc[2];
    acc[0] = 0ULL; acc[1] = 0ULL;
#pragma unroll 8
    for (int j = 0; j < 128; j++) {
        unsigned long long a2 = pack2(sA[rl * 129 + j]);
        ulonglong2 mv = *(const ulonglong2*)(sB + j * 128 + i0);
        acc[0] = ffma2(mv.x, a2, acc[0]);
        acc[1] = ffma2(mv.y, a2, acc[1]);
    }
#pragma unroll
    for (int e = 0; e < 2; e++) {
        float2 v = unpack2(acc[e]);
        int c0 = i0 + 2 * e;
        gE2[b * 16384 + r * 128 + c0]     = v.x;
        gE2[b * 16384 + r * 128 + c0 + 1] = v.y;
        gS[b * 16384 + r * 128 + c0]     = ((r == c0)     ? 1.0f : 0.0f) - sA[rl * 129 + c0]     + v.x;
        gS[b * 16384 + r * 128 + c0 + 1] = ((r == c0 + 1) ? 1.0f : 0.0f) - sA[rl * 129 + c0 + 1] + v.y;
    }
}

// ============================================================================
// kMM2: W = E2*S - E  (deg-4 Neumann; trunc ~1e-6) -> bf16 hi/lo.  grid 128 x 256.
// ============================================================================
__global__ __launch_bounds__(256, 1) void kMM2() {
    extern __shared__ float sm[];
    float* sA = sm;                 // E2 slice [8][129]
    float* sE = sm + 8 * 129;       // E slice  [8][129]
    float* sB = sm + 16 * 129;      // S full [128][128]
    const int b = blockIdx.x >> 4, r0 = (blockIdx.x & 15) * 8;
    const int t = threadIdx.x;
    for (int idx = t; idx < 1024; idx += 256) {
        int row = idx >> 7, j = idx & 127;
        sA[row * 129 + j] = gE2[b * 16384 + (r0 + row) * 128 + j];
        sE[row * 129 + j] = gE [b * 16384 + (r0 + row) * 128 + j];
    }
    for (int idx = t; idx < 4096; idx += 256)
        ((float4*)sB)[idx] = ((const float4*)(gS + b * 16384))[idx];
    __syncthreads();
    const int rl = t & 7, r = r0 + rl, k0 = (t >> 3) * 4;
    unsigned long long acc[2];
    acc[0] = 0ULL; acc[1] = 0ULL;
#pragma unroll 8
    for (int j = 0; j < 128; j++) {
        unsigned long long a2 = pack2(sA[rl * 129 + j]);
        ulonglong2 mv = *(const ulonglong2*)(sB + j * 128 + k0);
        acc[0] = ffma2(mv.x, a2, acc[0]);
        acc[1] = ffma2(mv.y, a2, acc[1]);
    }
    uint32_t* o1 = (uint32_t*)gW1 + b * 8192;
    uint32_t* o2 = (uint32_t*)gW2 + b * 8192;
#pragma unroll
    for (int e = 0; e < 2; e++) {
        float2 tv = unpack2(acc[e]);
        int k = k0 + 2 * e;
        float wx = tv.x - sE[rl * 129 + k];
        float wy = tv.y - sE[rl * 129 + k + 1];
        uint32_t hi, lo;
        split2(wx, wy, hi, lo);
        o1[r * 64 + (k >> 1)] = hi;
        o2[r * 64 + (k >> 1)] = lo;
    }
}

// ============================================================================
// k_admm: fused P-prep + 50 HMMA ADMM iters + epilogue.
// Fragment loads via ldmatrix.x4 (8 LDSM/k-step vs 32 LDS.32); values and MMA
// term order bit-identical to round 8 (k0 asc, Ah*W1, Al*W1, Ah*W2).
// ============================================================================
#define S136 136
#define SM_RH 0                  // rhs hi [128][136] bf16
#define SM_RL 34816
#define SM_W1 69632              // W hi (V in prologue, Vt in epilogue)
#define SM_W2 104448
#define SM_P  139264             // f32 [128][132]
#define SM_CNT 206848            // f32 [128][16]
#define SMEM_ADMM 215040
#define MT_STEP 4352             // 16 rows * 272 B

// 3-term split GEMM over the resident tiles; addresses are per-lane LDSM bases.
__device__ __forceinline__ void gemm3(float acc[2][4][4],
                                      uint32_t aH, uint32_t aL,
                                      uint32_t bW1, uint32_t bW2) {
#pragma unroll
    for (int k0 = 0; k0 < 8; k0++) {
        uint32_t off = (uint32_t)k0 * 32;
        uint32_t ah[2][4], al[2][4], b0v[4], b1v[4], c0v[4], c1v[4];
        LDSM4(ah[0][0], ah[0][1], ah[0][2], ah[0][3], aH + off);
        LDSM4(ah[1][0], ah[1][1], ah[1][2], ah[1][3], aH + MT_STEP + off);
        LDSM4(al[0][0], al[0][1], al[0][2], al[0][3], aL + off);
        LDSM4(al[1][0], al[1][1], al[1][2], al[1][3], aL + MT_STEP + off);
        LDSM4(b0v[0], b0v[1], b0v[2], b0v[3], bW1 + off);
        LDSM4(b1v[0], b1v[1], b1v[2], b1v[3], bW1 + 16 + off);
        LDSM4(c0v[0], c0v[1], c0v[2], c0v[3], bW2 + off);
        LDSM4(c1v[0], c1v[1], c1v[2], c1v[3], bW2 + 16 + off);
#pragma unroll
        for (int nt = 0; nt < 4; nt++)
#pragma unroll
            for (int mt = 0; mt < 2; mt++) {
                mma_bf16(acc[mt][nt], ah[mt][0], ah[mt][1], ah[mt][2], ah[mt][3], b0v[nt], b1v[nt]);
                mma_bf16(acc[mt][nt], al[mt][0], al[mt][1], al[mt][2], al[mt][3], b0v[nt], b1v[nt]);
                mma_bf16(acc[mt][nt], ah[mt][0], ah[mt][1], ah[mt][2], ah[mt][3], c0v[nt], c1v[nt]);
            }
    }
}

__global__ __launch_bounds__(512, 1) void k_admm(const float* __restrict__ gQ,
                                                 const float* __restrict__ gV,
                                                 float* __restrict__ gOut) {
    extern __shared__ char smem[];
    __nv_bfloat16* rhB = (__nv_bfloat16*)(smem + SM_RH);
    __nv_bfloat16* rlB = (__nv_bfloat16*)(smem + SM_RL);
    __nv_bfloat16* w1B = (__nv_bfloat16*)(smem + SM_W1);
    __nv_bfloat16* w2B = (__nv_bfloat16*)(smem + SM_W2);
    float* sP   = (float*)(smem + SM_P);
    float* sCnt = (float*)(smem + SM_CNT);

    const int t = threadIdx.x;
    const int lane = t & 31, w = t >> 5;
    const int g = w >> 3, wg = w & 7;
    const int mg = wg & 1, ng = wg >> 1;
    const int gid = lane >> 2, tig = lane & 3;
    const int m0 = g * 64 + mg * 32, n0 = ng * 32;
    const int rA = m0 + gid;
    const int b = blockIdx.x >> 4, row0 = (blockIdx.x & 15) * 128;
    const float* Vb = gV + b * 16384;
    const float* Qb = gQ + (size_t)(b * NN + row0) * 128;

    // per-lane LDSM base addresses (valid for all three GEMMs)
    const uint32_t sb = smem_u32(smem);
    const uint32_t aoff = (uint32_t)(m0 + ((lane >> 3) & 1) * 8 + (lane & 7)) * 272 +
                          (uint32_t)(lane >> 4) * 16;
    const uint32_t aH = sb + SM_RH + aoff;
    const uint32_t aL = sb + SM_RL + aoff;
    const uint32_t boff = (uint32_t)(n0 + 8 * (lane >> 3) + (lane & 7)) * 272;
    const uint32_t bW1 = sb + SM_W1 + boff;
    const uint32_t bW2 = sb + SM_W2 + boff;

    // ---- prologue: Q split -> rhs tiles; V split -> W tiles ----
    for (int idx = t; idx < 8192; idx += 512) {
        int row = idx >> 6, c2 = (idx & 63) * 2;
        float2 q = *(const float2*)(Qb + row * 128 + c2);
        uint32_t hi, lo;
        split2(q.x, q.y, hi, lo);
        *(uint32_t*)(rhB + row * S136 + c2) = hi;
        *(uint32_t*)(rlB + row * S136 + c2) = lo;
        float2 v = *(const float2*)(Vb + row * 128 + c2);
        split2(v.x, v.y, hi, lo);
        *(uint32_t*)(w1B + row * S136 + c2) = hi;
        *(uint32_t*)(w2B + row * S136 + c2) = lo;
    }
    __syncthreads();

    // ---- P = -(2/m) Q V^T + lambda/m ----
    {
        float acc[2][4][4];
#pragma unroll
        for (int mt = 0; mt < 2; mt++)
#pragma unroll
            for (int nt = 0; nt < 4; nt++)
#pragma unroll
                for (int j = 0; j < 4; j++) acc[mt][nt][j] = 0.0f;
        gemm3(acc, aH, aL, bW1, bW2);
        const float cP = -2.0f / 128.0f, cL = 0.1f / 128.0f;
#pragma unroll
        for (int mt = 0; mt < 2; mt++) {
            int ra = rA + 16 * mt, rb = ra + 8;
#pragma unroll
            for (int nt = 0; nt < 4; nt++) {
                int c = n0 + nt * 8 + 2 * tig;
                *(float2*)(sP + ra * 132 + c) = make_float2(cP * acc[mt][nt][0] + cL, cP * acc[mt][nt][1] + cL);
                *(float2*)(sP + rb * 132 + c) = make_float2(cP * acc[mt][nt][2] + cL, cP * acc[mt][nt][3] + cL);
            }
        }
    }
    __syncthreads();   // V-tile reads done

    // ---- load W bf16 hi/lo ----
    {
        const uint32_t* w1g = (const uint32_t*)gW1 + b * 8192;
        const uint32_t* w2g = (const uint32_t*)gW2 + b * 8192;
        for (int idx = t; idx < 8192; idx += 512) {
            int row = idx >> 6, cw = idx & 63;
            *(uint32_t*)(w1B + row * S136 + cw * 2) = w1g[row * 64 + cw];
            *(uint32_t*)(w2B + row * S136 + cw * 2) = w2g[row * 64 + cw];
        }
    }
    __syncthreads();

    float z[32], u[32];
#pragma unroll
    for (int e = 0; e < 32; e++) { z[e] = 0.0f; u[e] = 0.0f; }

    // ---- 50 ADMM iterations (group-synchronized) ----
    for (int it = 0; it < ITERS; it++) {
#pragma unroll
        for (int mt = 0; mt < 2; mt++) {
            int ra = rA + 16 * mt, rb = ra + 8;
#pragma unroll
            for (int nt = 0; nt < 4; nt++) {
                int e = mt * 16 + nt * 4;
                int c = n0 + nt * 8 + 2 * tig;
                float2 p0 = *(float2*)(sP + ra * 132 + c);
                float2 p1 = *(float2*)(sP + rb * 132 + c);
                uint32_t hi, lo;
                split2(z[e] - u[e] - p0.x, z[e + 1] - u[e + 1] - p0.y, hi, lo);
                *(uint32_t*)(rhB + ra * S136 + c) = hi;
                *(uint32_t*)(rlB + ra * S136 + c) = lo;
                split2(z[e + 2] - u[e + 2] - p1.x, z[e + 3] - u[e + 3] - p1.y, hi, lo);
                *(uint32_t*)(rhB + rb * S136 + c) = hi;
                *(uint32_t*)(rlB + rb * S136 + c) = lo;
            }
        }
        barg(1 + g);

        float acc[2][4][4];
#pragma unroll
        for (int mt = 0; mt < 2; mt++)
#pragma unroll
            for (int nt = 0; nt < 4; nt++)
#pragma unroll
                for (int j = 0; j < 4; j++) acc[mt][nt][j] = 0.0f;
        gemm3(acc, aH, aL, bW1, bW2);
        barg(1 + g);

#pragma unroll
        for (int mt = 0; mt < 2; mt++) {
            int ra = rA + 16 * mt, rb = ra + 8;
#pragma unroll
            for (int nt = 0; nt < 4; nt++) {
                int e = mt * 16 + nt * 4;
                int c = n0 + nt * 8 + 2 * tig;
                float2 p0 = *(float2*)(sP + ra * 132 + c);
                float2 p1 = *(float2*)(sP + rb * 132 + c);
                float pv[4] = {p0.x, p0.y, p1.x, p1.y};
#pragma unroll
                for (int j = 0; j < 4; j++) {
                    float rhs = z[e + j] - u[e + j] - pv[j];
                    float x = rhs + acc[mt][nt][j];
                    float xu = x + u[e + j];
                    float zn = fminf(fmaxf(xu, 0.0f), 1.0f);
                    u[e + j] = xu - zn;
                    z[e + j] = zn;
                }
            }
        }
    }

    // ---- epilogue ----
#pragma unroll
    for (int mt = 0; mt < 2; mt++) {
        int ra = rA + 16 * mt, rb = ra + 8;
        float c0s = 0.0f, c1s = 0.0f;
#pragma unroll
        for (int nt = 0; nt < 4; nt++) {
            int e = mt * 16 + nt * 4;
            c0s += ((z[e]     > 0.5f) ? 1.0f : 0.0f) + ((z[e + 1] > 0.5f) ? 1.0f : 0.0f);
            c1s += ((z[e + 2] > 0.5f) ? 1.0f : 0.0f) + ((z[e + 3] > 0.5f) ? 1.0f : 0.0f);
        }
        sCnt[ra * 16 + ng * 4 + tig] = c0s;
        sCnt[rb * 16 + ng * 4 + tig] = c1s;
    }
    barg(1 + g);
    float inv[2][2];
#pragma unroll
    for (int mt = 0; mt < 2; mt++) {
        int ra = rA + 16 * mt, rb = ra + 8;
        float s0 = 0.0f, s1 = 0.0f;
#pragma unroll
        for (int k = 0; k < 16; k++) { s0 += sCnt[ra * 16 + k]; s1 += sCnt[rb * 16 + k]; }
        inv[mt][0] = 1.0f / (128.0f * (s0 + 1e-10f));
        inv[mt][1] = 1.0f / (128.0f * (s1 + 1e-10f));
    }
#pragma unroll
    for (int mt = 0; mt < 2; mt++) {
        int ra = rA + 16 * mt, rb = ra + 8;
#pragma unroll
        for (int nt = 0; nt < 4; nt++) {
            int e = mt * 16 + nt * 4;
            int c = n0 + nt * 8 + 2 * tig;
            uint32_t hi, lo;
            split2((z[e]     > 0.5f) ? inv[mt][0] : 0.0f,
                   (z[e + 1] > 0.5f) ? inv[mt][0] : 0.0f, hi, lo);
            *(uint32_t*)(rhB + ra * S136 + c) = hi;
            *(uint32_t*)(rlB + ra * S136 + c) = lo;
            split2((z[e + 2] > 0.5f) ? inv[mt][1] : 0.0f,
                   (z[e + 3] > 0.5f) ? inv[mt][1] : 0.0f, hi, lo);
            *(uint32_t*)(rhB + rb * S136 + c) = hi;
            *(uint32_t*)(rlB + rb * S136 + c) = lo;
        }
    }
    __syncthreads();   // both groups done with W tiles + coeff writes
    for (int idx = t; idx < 16384; idx += 512) {
        int m = idx >> 7, d = idx & 127;
        float f = Vb[idx];
        __nv_bfloat16 h = __float2bfloat16(f);
        w1B[d * S136 + m] = h;
        w2B[d * S136 + m] = __float2bfloat16(f - __bfloat162float(h));
    }
    __syncthreads();

    {
        float acc[2][4][4];
#pragma unroll
        for (int mt = 0; mt < 2; mt++)
#pragma unroll
            for (int nt = 0; nt < 4; nt++)
#pragma unroll
                for (int j = 0; j < 4; j++) acc[mt][nt][j] = 0.0f;
        gemm3(acc, aH, aL, bW1, bW2);
        float* ob = gOut + (size_t)(b * NN + row0) * 128;
#pragma unroll
        for (int mt = 0; mt < 2; mt++) {
            int ra = rA + 16 * mt, rb = ra + 8;
#pragma unroll
            for (int nt = 0; nt < 4; nt++) {
                int c = n0 + nt * 8 + 2 * tig;
                *(float2*)(ob + ra * 128 + c) = make_float2(acc[mt][nt][0], acc[mt][nt][1]);
                *(float2*)(ob + rb * 128 + c) = make_float2(acc[mt][nt][2], acc[mt][nt][3]);
            }
        }
    }
}

// ============================================================================

extern "C" void kernel_launch(void* const* d_in, const int* in_sizes, int n_in,
                              void* d_out, int out_size) {
    const float* gQ = (const float*)d_in[0];
    const float* gV = (const float*)d_in[1];
    if (n_in >= 2 && in_sizes[0] == BB * 128 * 128 && in_sizes[1] == BB * NN * 128) {
        gV = (const float*)d_in[0];
        gQ = (const float*)d_in[1];
    }
    float* out = (float*)d_out;

    const int SMEM_E   = 128 * 132 * 4;                // 67584
    const int SMEM_MM1 = (8 * 129 + 128 * 128) * 4;    // 69664
    const int SMEM_MM2 = (16 * 129 + 128 * 128) * 4;   // 73792

    cudaFuncSetAttribute(kE,   cudaFuncAttributeMaxDynamicSharedMemorySize, SMEM_E);
    cudaFuncSetAttribute(kMM1, cudaFuncAttributeMaxDynamicSharedMemorySize, SMEM_MM1);
    cudaFuncSetAttribute(kMM2, cudaFuncAttributeMaxDynamicSharedMemorySize, SMEM_MM2);
    cudaFuncSetAttribute(k_admm, cudaFuncAttributeMaxDynamicSharedMemorySize, SMEM_ADMM);

    kE<<<64, 256, SMEM_E>>>(gV);
    kMM1<<<128, 256, SMEM_MM1>>>();       // E2 = E*E ; S = I - E + E2
    kMM2<<<128, 256, SMEM_MM2>>>();       // W = E2*S - E -> bf16 hi/lo
    k_admm<<<BB * (NN / 128), 512, SMEM_ADMM>>>(gQ, gV, out);
}

// round 11
// speedup vs baseline: 1.0957x; 1.0957x over previous
#include <cuda_runtime.h>
#include <cuda_bf16.h>
#include <cstdint>

#define BB 8
#define NN 2048
#define ITERS 50

// ---- device scratch (no allocs allowed) ----
__device__ float gE[BB * 16384], gE2[BB * 16384], gS[BB * 16384];
__device__ __nv_bfloat16 gW1[BB * 16384], gW2[BB * 16384];

// ---- f32x2 helpers (prep kernels) ----
__device__ __forceinline__ unsigned long long ffma2(unsigned long long a,
                                                    unsigned long long b,
                                                    unsigned long long c) {
    unsigned long long d;
    asm("fma.rn.f32x2 %0, %1, %2, %3;" : "=l"(d) : "l"(a), "l"(b), "l"(c));
    return d;
}
__device__ __forceinline__ unsigned long long pack2(float x) {
    union { unsigned long long u; float2 f; } c; c.f = make_float2(x, x); return c.u;
}
__device__ __forceinline__ float2 unpack2(unsigned long long v) {
    union { unsigned long long u; float2 f; } c; c.u = v; return c.f;
}

// ---- HMMA m16n8k16 bf16 -> f32 ----
__device__ __forceinline__ void mma_bf16(float c[4],
                                         uint32_t a0, uint32_t a1, uint32_t a2, uint32_t a3,
                                         uint32_t b0, uint32_t b1) {
    asm volatile(
        "mma.sync.aligned.m16n8k16.row.col.f32.bf16.bf16.f32 "
        "{%0,%1,%2,%3}, {%4,%5,%6,%7}, {%8,%9}, {%0,%1,%2,%3};"
        : "+f"(c[0]), "+f"(c[1]), "+f"(c[2]), "+f"(c[3])
        : "r"(a0), "r"(a1), "r"(a2), "r"(a3), "r"(b0), "r"(b1));
}

__device__ __forceinline__ void split2(float x, float y, uint32_t& hi, uint32_t& lo) {
    __nv_bfloat162 h = __float22bfloat162_rn(make_float2(x, y));
    float2 hb = __bfloat1622float2(h);
    __nv_bfloat162 l = __float22bfloat162_rn(make_float2(x - hb.x, y - hb.y));
    hi = *(uint32_t*)&h;
    lo = *(uint32_t*)&l;
}

__device__ __forceinline__ void barg(int id) {
    asm volatile("bar.sync %0, %1;" :: "r"(id), "r"(256) : "memory");
}

// ============================================================================
// kE: E = (1/8192) V V^T.  grid 64 x 256.
// ============================================================================
__global__ __launch_bounds__(256, 1) void kE(const float* __restrict__ gV) {
    extern __shared__ float sm[];
    float* sVt = sm;                         // [128][132]
    const int b = blockIdx.x >> 3, r0 = (blockIdx.x & 7) * 16;
    const int t = threadIdx.x;
    for (int idx = t; idx < 16384; idx += 256) {
        int m = idx >> 7, d = idx & 127;
        sVt[d * 132 + m] = gV[b * 16384 + idx];
    }
    __syncthreads();
    const int r = r0 + (t & 15), i0 = (t >> 4) * 8;
    unsigned long long acc[4];
#pragma unroll
    for (int e = 0; e < 4; e++) acc[e] = 0ULL;
#pragma unroll 8
    for (int d = 0; d < 128; d++) {
        unsigned long long a2 = pack2(sVt[d * 132 + r]);
        const ulonglong2* pm = (const ulonglong2*)(sVt + d * 132 + i0);
        ulonglong2 m0 = pm[0], m1 = pm[1];
        acc[0] = ffma2(m0.x, a2, acc[0]);
        acc[1] = ffma2(m0.y, a2, acc[1]);
        acc[2] = ffma2(m1.x, a2, acc[2]);
        acc[3] = ffma2(m1.y, a2, acc[3]);
    }
    const float sc = 1.0f / 8192.0f;
#pragma unroll
    for (int e = 0; e < 4; e++) {
        float2 v = unpack2(acc[e]);
        gE[b * 16384 + r * 128 + i0 + 2 * e]     = sc * v.x;
        gE[b * 16384 + r * 128 + i0 + 2 * e + 1] = sc * v.y;
    }
}

// ============================================================================
// kMM1: E2 = E*E ; S = I - E + E2.   grid 128 x 256.
// ============================================================================
__global__ __launch_bounds__(256, 1) void kMM1() {
    extern __shared__ float sm[];
    float* sA = sm;                 // E slice [8][129]
    float* sB = sm + 8 * 129;       // E full [128][128]
    const int b = blockIdx.x >> 4, r0 = (blockIdx.x & 15) * 8;
    const int t = threadIdx.x;
    for (int idx = t; idx < 1024; idx += 256) {
        int row = idx >> 7, j = idx & 127;
        sA[row * 129 + j] = gE[b * 16384 + (r0 + row) * 128 + j];
    }
    for (int idx = t; idx < 4096; idx += 256)
        ((float4*)sB)[idx] = ((const float4*)(gE + b * 16384))[idx];
    __syncthreads();
    const int rl = t & 7, r = r0 + rl, i0 = (t >> 3) * 4;
    unsigned long long acc[2];
    acc[0] = 0ULL; acc[1] = 0ULL;
#pragma unroll 8
    for (int j = 0; j < 128; j++) {
        unsigned long long a2 = pack2(sA[rl * 129 + j]);
        ulonglong2 mv = *(const ulonglong2*)(sB + j * 128 + i0);
        acc[0] = ffma2(mv.x, a2, acc[0]);
        acc[1] = ffma2(mv.y, a2, acc[1]);
    }
#pragma unroll
    for (int e = 0; e < 2; e++) {
        float2 v = unpack2(acc[e]);
        int c0 = i0 + 2 * e;
        gE2[b * 16384 + r * 128 + c0]     = v.x;
        gE2[b * 16384 + r * 128 + c0 + 1] = v.y;
        gS[b * 16384 + r * 128 + c0]     = ((r == c0)     ? 1.0f : 0.0f) - sA[rl * 129 + c0]     + v.x;
        gS[b * 16384 + r * 128 + c0 + 1] = ((r == c0 + 1) ? 1.0f : 0.0f) - sA[rl * 129 + c0 + 1] + v.y;
    }
}

// ============================================================================
// kMM2: W = E2*S - E  (deg-4 Neumann; trunc ~1e-6) -> bf16 hi/lo.  grid 128 x 256.
// ============================================================================
__global__ __launch_bounds__(256, 1) void kMM2() {
    extern __shared__ float sm[];
    float* sA = sm;                 // E2 slice [8][129]
    float* sE = sm + 8 * 129;       // E slice  [8][129]
    float* sB = sm + 16 * 129;      // S full [128][128]
    const int b = blockIdx.x >> 4, r0 = (blockIdx.x & 15) * 8;
    const int t = threadIdx.x;
    for (int idx = t; idx < 1024; idx += 256) {
        int row = idx >> 7, j = idx & 127;
        sA[row * 129 + j] = gE2[b * 16384 + (r0 + row) * 128 + j];
        sE[row * 129 + j] = gE [b * 16384 + (r0 + row) * 128 + j];
    }
    for (int idx = t; idx < 4096; idx += 256)
        ((float4*)sB)[idx] = ((const float4*)(gS + b * 16384))[idx];
    __syncthreads();
    const int rl = t & 7, r = r0 + rl, k0 = (t >> 3) * 4;
    unsigned long long acc[2];
    acc[0] = 0ULL; acc[1] = 0ULL;
#pragma unroll 8
    for (int j = 0; j < 128; j++) {
        unsigned long long a2 = pack2(sA[rl * 129 + j]);
        ulonglong2 mv = *(const ulonglong2*)(sB + j * 128 + k0);
        acc[0] = ffma2(mv.x, a2, acc[0]);
        acc[1] = ffma2(mv.y, a2, acc[1]);
    }
    uint32_t* o1 = (uint32_t*)gW1 + b * 8192;
    uint32_t* o2 = (uint32_t*)gW2 + b * 8192;
#pragma unroll
    for (int e = 0; e < 2; e++) {
        float2 tv = unpack2(acc[e]);
        int k = k0 + 2 * e;
        float wx = tv.x - sE[rl * 129 + k];
        float wy = tv.y - sE[rl * 129 + k + 1];
        uint32_t hi, lo;
        split2(wx, wy, hi, lo);
        o1[r * 64 + (k >> 1)] = hi;
        o2[r * 64 + (k >> 1)] = lo;
    }
}

// ============================================================================
// k_admm: fused P-prep + 50 HMMA ADMM iters + epilogue.
// Round-8 arithmetic chain bit-identical; P in registers (no sP); single state
// xu (z/u derived, bitwise-equal expressions); double-buffered rhs tiles ->
// one named barrier per iteration. bf16, 3-term split (Ah*W1, Al*W1, Ah*W2).
// ============================================================================
#define S136 136
#define SM_B0H 0                 // rhs buf0 hi [128][136] bf16
#define SM_B0L 34816
#define SM_B1H 69632             // rhs buf1 hi/lo
#define SM_B1L 104448
#define SM_W1  139264            // W hi (V hi in prologue / Vt hi in epilogue)
#define SM_W2  174080
#define SM_CNT 208896            // f32 [128][16]
#define SMEM_ADMM 217088

// 3-term split GEMM, scalar LDS fragment loads (round-8 proven form).
__device__ __forceinline__ void gemm3s(float acc[2][4][4],
                                       const __nv_bfloat16* __restrict__ rhB,
                                       const __nv_bfloat16* __restrict__ rlB,
                                       const __nv_bfloat16* __restrict__ w1B,
                                       const __nv_bfloat16* __restrict__ w2B,
                                       int rA, int n0, int tig) {
#pragma unroll
    for (int k0 = 0; k0 < 8; k0++) {
        int ka = k0 * 16 + 2 * tig;
        uint32_t ah[2][4], al[2][4];
#pragma unroll
        for (int mt = 0; mt < 2; mt++) {
            int ra = rA + 16 * mt, rb = ra + 8;
            ah[mt][0] = *(const uint32_t*)(rhB + ra * S136 + ka);
            ah[mt][1] = *(const uint32_t*)(rhB + rb * S136 + ka);
            ah[mt][2] = *(const uint32_t*)(rhB + ra * S136 + ka + 8);
            ah[mt][3] = *(const uint32_t*)(rhB + rb * S136 + ka + 8);
            al[mt][0] = *(const uint32_t*)(rlB + ra * S136 + ka);
            al[mt][1] = *(const uint32_t*)(rlB + rb * S136 + ka);
            al[mt][2] = *(const uint32_t*)(rlB + ra * S136 + ka + 8);
            al[mt][3] = *(const uint32_t*)(rlB + rb * S136 + ka + 8);
        }
#pragma unroll
        for (int nt = 0; nt < 4; nt++) {
            int bn = n0 + nt * 8 + ((ka - 2 * tig) >> 4, 0);  // keep layout; bn uses gid below
            (void)bn;
        }
#pragma unroll
        for (int nt = 0; nt < 4; nt++) {
            // gid is encoded via rA? No: B row = n0 + nt*8 + gid; gid passed via rA? Use tig-free:
            // (resolved by caller passing n0 already including nothing; we need gid)
            ;
        }
        // NOTE: B-row needs gid; recompute from lane below via asm-free path.
        // (This placeholder loop removed — real B loads are in the macro below.)
        {
            int gid;
            asm("mov.u32 %0, %%laneid;" : "=r"(gid));
            gid = (gid >> 2);
#pragma unroll
            for (int nt = 0; nt < 4; nt++) {
                int bn = n0 + nt * 8 + gid;
                uint32_t b0 = *(const uint32_t*)(w1B + bn * S136 + ka);
                uint32_t b1 = *(const uint32_t*)(w1B + bn * S136 + ka + 8);
                uint32_t c0 = *(const uint32_t*)(w2B + bn * S136 + ka);
                uint32_t c1 = *(const uint32_t*)(w2B + bn * S136 + ka + 8);
#pragma unroll
                for (int mt = 0; mt < 2; mt++) {
                    mma_bf16(acc[mt][nt], ah[mt][0], ah[mt][1], ah[mt][2], ah[mt][3], b0, b1);
                    mma_bf16(acc[mt][nt], al[mt][0], al[mt][1], al[mt][2], al[mt][3], b0, b1);
                    mma_bf16(acc[mt][nt], ah[mt][0], ah[mt][1], ah[mt][2], ah[mt][3], c0, c1);
                }
            }
        }
    }
}

__global__ __launch_bounds__(512, 1) void k_admm(const float* __restrict__ gQ,
                                                 const float* __restrict__ gV,
                                                 float* __restrict__ gOut) {
    extern __shared__ char smem[];
    __nv_bfloat16* rh0 = (__nv_bfloat16*)(smem + SM_B0H);
    __nv_bfloat16* rl0 = (__nv_bfloat16*)(smem + SM_B0L);
    __nv_bfloat16* rh1 = (__nv_bfloat16*)(smem + SM_B1H);
    __nv_bfloat16* rl1 = (__nv_bfloat16*)(smem + SM_B1L);
    __nv_bfloat16* w1B = (__nv_bfloat16*)(smem + SM_W1);
    __nv_bfloat16* w2B = (__nv_bfloat16*)(smem + SM_W2);
    float* sCnt = (float*)(smem + SM_CNT);

    const int t = threadIdx.x;
    const int lane = t & 31, w = t >> 5;
    const int g = w >> 3, wg = w & 7;
    const int mg = wg & 1, ng = wg >> 1;
    const int gid = lane >> 2, tig = lane & 3;
    const int m0 = g * 64 + mg * 32, n0 = ng * 32;
    const int rA = m0 + gid;
    const int b = blockIdx.x >> 4, row0 = (blockIdx.x & 15) * 128;
    const float* Vb = gV + b * 16384;
    const float* Qb = gQ + (size_t)(b * NN + row0) * 128;

    // ---- prologue: Q split -> buf0; V split -> W tiles ----
    for (int idx = t; idx < 8192; idx += 512) {
        int row = idx >> 6, c2 = (idx & 63) * 2;
        float2 q = *(const float2*)(Qb + row * 128 + c2);
        uint32_t hi, lo;
        split2(q.x, q.y, hi, lo);
        *(uint32_t*)(rh0 + row * S136 + c2) = hi;
        *(uint32_t*)(rl0 + row * S136 + c2) = lo;
        float2 v = *(const float2*)(Vb + row * 128 + c2);
        split2(v.x, v.y, hi, lo);
        *(uint32_t*)(w1B + row * S136 + c2) = hi;
        *(uint32_t*)(w2B + row * S136 + c2) = lo;
    }
    __syncthreads();

    // ---- P = -(2/m) Q V^T + lambda/m -> registers ----
    float P[32];
    {
        float acc[2][4][4];
#pragma unroll
        for (int mt = 0; mt < 2; mt++)
#pragma unroll
            for (int nt = 0; nt < 4; nt++)
#pragma unroll
                for (int j = 0; j < 4; j++) acc[mt][nt][j] = 0.0f;
        gemm3s(acc, rh0, rl0, w1B, w2B, rA, n0, tig);
        const float cP = -2.0f / 128.0f, cL = 0.1f / 128.0f;
#pragma unroll
        for (int mt = 0; mt < 2; mt++)
#pragma unroll
            for (int nt = 0; nt < 4; nt++)
#pragma unroll
                for (int j = 0; j < 4; j++)
                    P[mt * 16 + nt * 4 + j] = cP * acc[mt][nt][j] + cL;
    }
    __syncthreads();   // Q/V tile reads done

    // ---- load W bf16 hi/lo ----
    {
        const uint32_t* w1g = (const uint32_t*)gW1 + b * 8192;
        const uint32_t* w2g = (const uint32_t*)gW2 + b * 8192;
        for (int idx = t; idx < 8192; idx += 512) {
            int row = idx >> 6, cw = idx & 63;
            *(uint32_t*)(w1B + row * S136 + cw * 2) = w1g[row * 64 + cw];
            *(uint32_t*)(w2B + row * S136 + cw * 2) = w2g[row * 64 + cw];
        }
    }

    float xu[32];
#pragma unroll
    for (int e = 0; e < 32; e++) xu[e] = 0.0f;

    // initial rhs (it=0): z=u=0 -> (0-0)-P, into buf0
#pragma unroll
    for (int mt = 0; mt < 2; mt++) {
        int ra = rA + 16 * mt, rb = ra + 8;
#pragma unroll
        for (int nt = 0; nt < 4; nt++) {
            int e = mt * 16 + nt * 4;
            int c = n0 + nt * 8 + 2 * tig;
            uint32_t hi, lo;
            split2((0.0f - 0.0f) - P[e], (0.0f - 0.0f) - P[e + 1], hi, lo);
            *(uint32_t*)(rh0 + ra * S136 + c) = hi;
            *(uint32_t*)(rl0 + ra * S136 + c) = lo;
            split2((0.0f - 0.0f) - P[e + 2], (0.0f - 0.0f) - P[e + 3], hi, lo);
            *(uint32_t*)(rh0 + rb * S136 + c) = hi;
            *(uint32_t*)(rl0 + rb * S136 + c) = lo;
        }
    }
    __syncthreads();   // covers W load + initial rhs

    // ---- 50 ADMM iterations: GEMM(buf p) -> pointwise -> write buf 1-p -> bar ----
    for (int it = 0; it < ITERS; it++) {
        const __nv_bfloat16* rhR = (it & 1) ? rh1 : rh0;
        const __nv_bfloat16* rlR = (it & 1) ? rl1 : rl0;
        __nv_bfloat16* rhW = (it & 1) ? rh0 : rh1;
        __nv_bfloat16* rlW = (it & 1) ? rl0 : rl1;

        float acc[2][4][4];
#pragma unroll
        for (int mt = 0; mt < 2; mt++)
#pragma unroll
            for (int nt = 0; nt < 4; nt++)
#pragma unroll
                for (int j = 0; j < 4; j++) acc[mt][nt][j] = 0.0f;
        gemm3s(acc, rhR, rlR, w1B, w2B, rA, n0, tig);

        // pointwise (round-8 chain, z/u derived from xu bitwise-identically)
#pragma unroll
        for (int mt = 0; mt < 2; mt++)
#pragma unroll
            for (int nt = 0; nt < 4; nt++)
#pragma unroll
                for (int j = 0; j < 4; j++) {
                    int e = mt * 16 + nt * 4 + j;
                    float zd = fminf(fmaxf(xu[e], 0.0f), 1.0f);
                    float ud = xu[e] - zd;
                    float rhs = (zd - ud) - P[e];
                    float x = rhs + acc[mt][nt][j];
                    xu[e] = x + ud;
                }

        // write next rhs into the other buffer
#pragma unroll
        for (int mt = 0; mt < 2; mt++) {
            int ra = rA + 16 * mt, rb = ra + 8;
#pragma unroll
            for (int nt = 0; nt < 4; nt++) {
                int e = mt * 16 + nt * 4;
                int c = n0 + nt * 8 + 2 * tig;
                float r4[4];
#pragma unroll
                for (int j = 0; j < 4; j++) {
                    float zd = fminf(fmaxf(xu[e + j], 0.0f), 1.0f);
                    float ud = xu[e + j] - zd;
                    r4[j] = (zd - ud) - P[e + j];
                }
                uint32_t hi, lo;
                split2(r4[0], r4[1], hi, lo);
                *(uint32_t*)(rhW + ra * S136 + c) = hi;
                *(uint32_t*)(rlW + ra * S136 + c) = lo;
                split2(r4[2], r4[3], hi, lo);
                *(uint32_t*)(rhW + rb * S136 + c) = hi;
                *(uint32_t*)(rlW + rb * S136 + c) = lo;
            }
        }
        barg(1 + g);
    }

    // ---- epilogue: counts, coeffs, out = coeff * (V/128) ----
    float z[32];
#pragma unroll
    for (int e = 0; e < 32; e++) z[e] = fminf(fmaxf(xu[e], 0.0f), 1.0f);
#pragma unroll
    for (int mt = 0; mt < 2; mt++) {
        int ra = rA + 16 * mt, rb = ra + 8;
        float c0s = 0.0f, c1s = 0.0f;
#pragma unroll
        for (int nt = 0; nt < 4; nt++) {
            int e = mt * 16 + nt * 4;
            c0s += ((z[e]     > 0.5f) ? 1.0f : 0.0f) + ((z[e + 1] > 0.5f) ? 1.0f : 0.0f);
            c1s += ((z[e + 2] > 0.5f) ? 1.0f : 0.0f) + ((z[e + 3] > 0.5f) ? 1.0f : 0.0f);
        }
        sCnt[ra * 16 + ng * 4 + tig] = c0s;
        sCnt[rb * 16 + ng * 4 + tig] = c1s;
    }
    barg(1 + g);
    float inv[2][2];
#pragma unroll
    for (int mt = 0; mt < 2; mt++) {
        int ra = rA + 16 * mt, rb = ra + 8;
        float s0 = 0.0f, s1 = 0.0f;
#pragma unroll
        for (int k = 0; k < 16; k++) { s0 += sCnt[ra * 16 + k]; s1 += sCnt[rb * 16 + k]; }
        inv[mt][0] = 1.0f / (128.0f * (s0 + 1e-10f));
        inv[mt][1] = 1.0f / (128.0f * (s1 + 1e-10f));
    }
#pragma unroll
    for (int mt = 0; mt < 2; mt++) {
        int ra = rA + 16 * mt, rb = ra + 8;
#pragma unroll
        for (int nt = 0; nt < 4; nt++) {
            int e = mt * 16 + nt * 4;
            int c = n0 + nt * 8 + 2 * tig;
            uint32_t hi, lo;
            split2((z[e]     > 0.5f) ? inv[mt][0] : 0.0f,
                   (z[e + 1] > 0.5f) ? inv[mt][0] : 0.0f, hi, lo);
            *(uint32_t*)(rh0 + ra * S136 + c) = hi;
            *(uint32_t*)(rl0 + ra * S136 + c) = lo;
            split2((z[e + 2] > 0.5f) ? inv[mt][1] : 0.0f,
                   (z[e + 3] > 0.5f) ? inv[mt][1] : 0.0f, hi, lo);
            *(uint32_t*)(rh0 + rb * S136 + c) = hi;
            *(uint32_t*)(rl0 + rb * S136 + c) = lo;
        }
    }
    __syncthreads();   // last-iter W reads + coeff writes done (both groups)
    for (int idx = t; idx < 16384; idx += 512) {
        int m = idx >> 7, d = idx & 127;
        float f = Vb[idx];
        __nv_bfloat16 h = __float2bfloat16(f);
        w1B[d * S136 + m] = h;
        w2B[d * S136 + m] = __float2bfloat16(f - __bfloat162float(h));
    }
    __syncthreads();

    {
        float acc[2][4][4];
#pragma unroll
        for (int mt = 0; mt < 2; mt++)
#pragma unroll
            for (int nt = 0; nt < 4; nt++)
#pragma unroll
                for (int j = 0; j < 4; j++) acc[mt][nt][j] = 0.0f;
        gemm3s(acc, rh0, rl0, w1B, w2B, rA, n0, tig);
        float* ob = gOut + (size_t)(b * NN + row0) * 128;
#pragma unroll
        for (int mt = 0; mt < 2; mt++) {
            int ra = rA + 16 * mt, rb = ra + 8;
#pragma unroll
            for (int nt = 0; nt < 4; nt++) {
                int c = n0 + nt * 8 + 2 * tig;
                *(float2*)(ob + ra * 128 + c) = make_float2(acc[mt][nt][0], acc[mt][nt][1]);
                *(float2*)(ob + rb * 128 + c) = make_float2(acc[mt][nt][2], acc[mt][nt][3]);
            }
        }
    }
}

// ============================================================================

extern "C" void kernel_launch(void* const* d_in, const int* in_sizes, int n_in,
                              void* d_out, int out_size) {
    const float* gQ = (const float*)d_in[0];
    const float* gV = (const float*)d_in[1];
    if (n_in >= 2 && in_sizes[0] == BB * 128 * 128 && in_sizes[1] == BB * NN * 128) {
        gV = (const float*)d_in[0];
        gQ = (const float*)d_in[1];
    }
    float* out = (float*)d_out;

    const int SMEM_E   = 128 * 132 * 4;                // 67584
    const int SMEM_MM1 = (8 * 129 + 128 * 128) * 4;    // 69664
    const int SMEM_MM2 = (16 * 129 + 128 * 128) * 4;   // 73792

    cudaFuncSetAttribute(kE,   cudaFuncAttributeMaxDynamicSharedMemorySize, SMEM_E);
    cudaFuncSetAttribute(kMM1, cudaFuncAttributeMaxDynamicSharedMemorySize, SMEM_MM1);
    cudaFuncSetAttribute(kMM2, cudaFuncAttributeMaxDynamicSharedMemorySize, SMEM_MM2);
    cudaFuncSetAttribute(k_admm, cudaFuncAttributeMaxDynamicSharedMemorySize, SMEM_ADMM);

    kE<<<64, 256, SMEM_E>>>(gV);
    kMM1<<<128, 256, SMEM_MM1>>>();       // E2 = E*E ; S = I - E + E2
    kMM2<<<128, 256, SMEM_MM2>>>();       // W = E2*S - E -> bf16 hi/lo
    k_admm<<<BB * (NN / 128), 512, SMEM_ADMM>>>(gQ, gV, out);
}

// round 12
// speedup vs baseline: 1.1070x; 1.0103x over previous
#include <cuda_runtime.h>
#include <cuda_bf16.h>
#include <cstdint>

#define BB 8
#define NN 2048
#define ITERS 50

// ---- device scratch (no allocs allowed) ----
__device__ float gE[BB * 16384], gE2[BB * 16384], gS[BB * 16384];
__device__ __nv_bfloat16 gW1[BB * 16384], gW2[BB * 16384];

// ---- f32x2 helpers (prep kernels) ----
__device__ __forceinline__ unsigned long long ffma2(unsigned long long a,
                                                    unsigned long long b,
                                                    unsigned long long c) {
    unsigned long long d;
    asm("fma.rn.f32x2 %0, %1, %2, %3;" : "=l"(d) : "l"(a), "l"(b), "l"(c));
    return d;
}
__device__ __forceinline__ unsigned long long pack2(float x) {
    union { unsigned long long u; float2 f; } c; c.f = make_float2(x, x); return c.u;
}
__device__ __forceinline__ float2 unpack2(unsigned long long v) {
    union { unsigned long long u; float2 f; } c; c.u = v; return c.f;
}

// ---- HMMA m16n8k16 bf16 -> f32 ----
__device__ __forceinline__ void mma_bf16(float c[4],
                                         uint32_t a0, uint32_t a1, uint32_t a2, uint32_t a3,
                                         uint32_t b0, uint32_t b1) {
    asm volatile(
        "mma.sync.aligned.m16n8k16.row.col.f32.bf16.bf16.f32 "
        "{%0,%1,%2,%3}, {%4,%5,%6,%7}, {%8,%9}, {%0,%1,%2,%3};"
        : "+f"(c[0]), "+f"(c[1]), "+f"(c[2]), "+f"(c[3])
        : "r"(a0), "r"(a1), "r"(a2), "r"(a3), "r"(b0), "r"(b1));
}

__device__ __forceinline__ void split2(float x, float y, uint32_t& hi, uint32_t& lo) {
    __nv_bfloat162 h = __float22bfloat162_rn(make_float2(x, y));
    float2 hb = __bfloat1622float2(h);
    __nv_bfloat162 l = __float22bfloat162_rn(make_float2(x - hb.x, y - hb.y));
    hi = *(uint32_t*)&h;
    lo = *(uint32_t*)&l;
}

__device__ __forceinline__ void barg128(int id) {
    asm volatile("bar.sync %0, %1;" :: "r"(id), "r"(128) : "memory");
}

// ============================================================================
// kE: E = (1/8192) V V^T.  grid 64 x 256.
// ============================================================================
__global__ __launch_bounds__(256, 1) void kE(const float* __restrict__ gV) {
    extern __shared__ float sm[];
    float* sVt = sm;                         // [128][132]
    const int b = blockIdx.x >> 3, r0 = (blockIdx.x & 7) * 16;
    const int t = threadIdx.x;
    for (int idx = t; idx < 16384; idx += 256) {
        int m = idx >> 7, d = idx & 127;
        sVt[d * 132 + m] = gV[b * 16384 + idx];
    }
    __syncthreads();
    const int r = r0 + (t & 15), i0 = (t >> 4) * 8;
    unsigned long long acc[4];
#pragma unroll
    for (int e = 0; e < 4; e++) acc[e] = 0ULL;
#pragma unroll 8
    for (int d = 0; d < 128; d++) {
        unsigned long long a2 = pack2(sVt[d * 132 + r]);
        const ulonglong2* pm = (const ulonglong2*)(sVt + d * 132 + i0);
        ulonglong2 m0 = pm[0], m1 = pm[1];
        acc[0] = ffma2(m0.x, a2, acc[0]);
        acc[1] = ffma2(m0.y, a2, acc[1]);
        acc[2] = ffma2(m1.x, a2, acc[2]);
        acc[3] = ffma2(m1.y, a2, acc[3]);
    }
    const float sc = 1.0f / 8192.0f;
#pragma unroll
    for (int e = 0; e < 4; e++) {
        float2 v = unpack2(acc[e]);
        gE[b * 16384 + r * 128 + i0 + 2 * e]     = sc * v.x;
        gE[b * 16384 + r * 128 + i0 + 2 * e + 1] = sc * v.y;
    }
}

// ============================================================================
// kMM1: E2 = E*E ; S = I - E + E2.   grid 128 x 256.
// ============================================================================
__global__ __launch_bounds__(256, 1) void kMM1() {
    extern __shared__ float sm[];
    float* sA = sm;                 // E slice [8][129]
    float* sB = sm + 8 * 129;       // E full [128][128]
    const int b = blockIdx.x >> 4, r0 = (blockIdx.x & 15) * 8;
    const int t = threadIdx.x;
    for (int idx = t; idx < 1024; idx += 256) {
        int row = idx >> 7, j = idx & 127;
        sA[row * 129 + j] = gE[b * 16384 + (r0 + row) * 128 + j];
    }
    for (int idx = t; idx < 4096; idx += 256)
        ((float4*)sB)[idx] = ((const float4*)(gE + b * 16384))[idx];
    __syncthreads();
    const int rl = t & 7, r = r0 + rl, i0 = (t >> 3) * 4;
    unsigned long long acc[2];
    acc[0] = 0ULL; acc[1] = 0ULL;
#pragma unroll 8
    for (int j = 0; j < 128; j++) {
        unsigned long long a2 = pack2(sA[rl * 129 + j]);
        ulonglong2 mv = *(const ulonglong2*)(sB + j * 128 + i0);
        acc[0] = ffma2(mv.x, a2, acc[0]);
        acc[1] = ffma2(mv.y, a2, acc[1]);
    }
#pragma unroll
    for (int e = 0; e < 2; e++) {
        float2 v = unpack2(acc[e]);
        int c0 = i0 + 2 * e;
        gE2[b * 16384 + r * 128 + c0]     = v.x;
        gE2[b * 16384 + r * 128 + c0 + 1] = v.y;
        gS[b * 16384 + r * 128 + c0]     = ((r == c0)     ? 1.0f : 0.0f) - sA[rl * 129 + c0]     + v.x;
        gS[b * 16384 + r * 128 + c0 + 1] = ((r == c0 + 1) ? 1.0f : 0.0f) - sA[rl * 129 + c0 + 1] + v.y;
    }
}

// ============================================================================
// kMM2: W = E2*S - E  (deg-4 Neumann; trunc ~1e-6) -> bf16 hi/lo.  grid 128 x 256.
// ============================================================================
__global__ __launch_bounds__(256, 1) void kMM2() {
    extern __shared__ float sm[];
    float* sA = sm;                 // E2 slice [8][129]
    float* sE = sm + 8 * 129;       // E slice  [8][129]
    float* sB = sm + 16 * 129;      // S full [128][128]
    const int b = blockIdx.x >> 4, r0 = (blockIdx.x & 15) * 8;
    const int t = threadIdx.x;
    for (int idx = t; idx < 1024; idx += 256) {
        int row = idx >> 7, j = idx & 127;
        sA[row * 129 + j] = gE2[b * 16384 + (r0 + row) * 128 + j];
        sE[row * 129 + j] = gE [b * 16384 + (r0 + row) * 128 + j];
    }
    for (int idx = t; idx < 4096; idx += 256)
        ((float4*)sB)[idx] = ((const float4*)(gS + b * 16384))[idx];
    __syncthreads();
    const int rl = t & 7, r = r0 + rl, k0 = (t >> 3) * 4;
    unsigned long long acc[2];
    acc[0] = 0ULL; acc[1] = 0ULL;
#pragma unroll 8
    for (int j = 0; j < 128; j++) {
        unsigned long long a2 = pack2(sA[rl * 129 + j]);
        ulonglong2 mv = *(const ulonglong2*)(sB + j * 128 + k0);
        acc[0] = ffma2(mv.x, a2, acc[0]);
        acc[1] = ffma2(mv.y, a2, acc[1]);
    }
    uint32_t* o1 = (uint32_t*)gW1 + b * 8192;
    uint32_t* o2 = (uint32_t*)gW2 + b * 8192;
#pragma unroll
    for (int e = 0; e < 2; e++) {
        float2 tv = unpack2(acc[e]);
        int k = k0 + 2 * e;
        float wx = tv.x - sE[rl * 129 + k];
        float wy = tv.y - sE[rl * 129 + k + 1];
        uint32_t hi, lo;
        split2(wx, wy, hi, lo);
        o1[r * 64 + (k >> 1)] = hi;
        o2[r * 64 + (k >> 1)] = lo;
    }
}

// ============================================================================
// k_admm: fused P-prep + 50 HMMA ADMM iters + epilogue.
// 4 independent 128-thread groups (rows 32g..32g+31) with named barriers; one
// warp of each group per SMSP -> fine-grained drift keeps tensor pipe busy.
// Double-buffered rhs tiles, one barrier/iter. Arithmetic chain bit-identical
// to rounds 8/11 (k0 asc; Ah*W1, Al*W1, Ah*W2).
// ============================================================================
#define S136 136
#define SM_B0H 0                 // rhs buf0 hi [128][136] bf16
#define SM_B0L 34816
#define SM_B1H 69632             // rhs buf1 hi/lo
#define SM_B1L 104448
#define SM_W1  139264            // W hi (V hi in prologue / Vt hi in epilogue)
#define SM_W2  174080
#define SM_CNT 208896            // f32 [128][16]
#define SMEM_ADMM 217088

// 3-term split GEMM, scalar LDS fragment loads (round-8 proven form).
__device__ __forceinline__ void gemm3s(float acc[2][4][4],
                                       const __nv_bfloat16* __restrict__ rhB,
                                       const __nv_bfloat16* __restrict__ rlB,
                                       const __nv_bfloat16* __restrict__ w1B,
                                       const __nv_bfloat16* __restrict__ w2B,
                                       int rA, int n0, int tig, int gid) {
#pragma unroll
    for (int k0 = 0; k0 < 8; k0++) {
        int ka = k0 * 16 + 2 * tig;
        uint32_t ah[2][4], al[2][4];
#pragma unroll
        for (int mt = 0; mt < 2; mt++) {
            int ra = rA + 16 * mt, rb = ra + 8;
            ah[mt][0] = *(const uint32_t*)(rhB + ra * S136 + ka);
            ah[mt][1] = *(const uint32_t*)(rhB + rb * S136 + ka);
            ah[mt][2] = *(const uint32_t*)(rhB + ra * S136 + ka + 8);
            ah[mt][3] = *(const uint32_t*)(rhB + rb * S136 + ka + 8);
            al[mt][0] = *(const uint32_t*)(rlB + ra * S136 + ka);
            al[mt][1] = *(const uint32_t*)(rlB + rb * S136 + ka);
            al[mt][2] = *(const uint32_t*)(rlB + ra * S136 + ka + 8);
            al[mt][3] = *(const uint32_t*)(rlB + rb * S136 + ka + 8);
        }
#pragma unroll
        for (int nt = 0; nt < 4; nt++) {
            int bn = n0 + nt * 8 + gid;
            uint32_t b0 = *(const uint32_t*)(w1B + bn * S136 + ka);
            uint32_t b1 = *(const uint32_t*)(w1B + bn * S136 + ka + 8);
            uint32_t c0 = *(const uint32_t*)(w2B + bn * S136 + ka);
            uint32_t c1 = *(const uint32_t*)(w2B + bn * S136 + ka + 8);
#pragma unroll
            for (int mt = 0; mt < 2; mt++) {
                mma_bf16(acc[mt][nt], ah[mt][0], ah[mt][1], ah[mt][2], ah[mt][3], b0, b1);
                mma_bf16(acc[mt][nt], al[mt][0], al[mt][1], al[mt][2], al[mt][3], b0, b1);
                mma_bf16(acc[mt][nt], ah[mt][0], ah[mt][1], ah[mt][2], ah[mt][3], c0, c1);
            }
        }
    }
}

__global__ __launch_bounds__(512, 1) void k_admm(const float* __restrict__ gQ,
                                                 const float* __restrict__ gV,
                                                 float* __restrict__ gOut) {
    extern __shared__ char smem[];
    __nv_bfloat16* rh0 = (__nv_bfloat16*)(smem + SM_B0H);
    __nv_bfloat16* rl0 = (__nv_bfloat16*)(smem + SM_B0L);
    __nv_bfloat16* rh1 = (__nv_bfloat16*)(smem + SM_B1H);
    __nv_bfloat16* rl1 = (__nv_bfloat16*)(smem + SM_B1L);
    __nv_bfloat16* w1B = (__nv_bfloat16*)(smem + SM_W1);
    __nv_bfloat16* w2B = (__nv_bfloat16*)(smem + SM_W2);
    float* sCnt = (float*)(smem + SM_CNT);

    const int t = threadIdx.x;
    const int lane = t & 31, w = t >> 5;
    const int g = w >> 2;                 // 4 groups of 4 warps (one warp/SMSP each)
    const int wg2 = w & 3;                // column slice within group
    const int gid = lane >> 2, tig = lane & 3;
    const int m0 = g * 32, n0 = wg2 * 32;
    const int rA = m0 + gid;
    const int b = blockIdx.x >> 4, row0 = (blockIdx.x & 15) * 128;
    const float* Vb = gV + b * 16384;
    const float* Qb = gQ + (size_t)(b * NN + row0) * 128;

    // ---- prologue: Q split -> buf0; V split -> W tiles ----
    for (int idx = t; idx < 8192; idx += 512) {
        int row = idx >> 6, c2 = (idx & 63) * 2;
        float2 q = *(const float2*)(Qb + row * 128 + c2);
        uint32_t hi, lo;
        split2(q.x, q.y, hi, lo);
        *(uint32_t*)(rh0 + row * S136 + c2) = hi;
        *(uint32_t*)(rl0 + row * S136 + c2) = lo;
        float2 v = *(const float2*)(Vb + row * 128 + c2);
        split2(v.x, v.y, hi, lo);
        *(uint32_t*)(w1B + row * S136 + c2) = hi;
        *(uint32_t*)(w2B + row * S136 + c2) = lo;
    }
    __syncthreads();

    // ---- P = -(2/m) Q V^T + lambda/m -> registers ----
    float P[32];
    {
        float acc[2][4][4];
#pragma unroll
        for (int mt = 0; mt < 2; mt++)
#pragma unroll
            for (int nt = 0; nt < 4; nt++)
#pragma unroll
                for (int j = 0; j < 4; j++) acc[mt][nt][j] = 0.0f;
        gemm3s(acc, rh0, rl0, w1B, w2B, rA, n0, tig, gid);
        const float cP = -2.0f / 128.0f, cL = 0.1f / 128.0f;
#pragma unroll
        for (int mt = 0; mt < 2; mt++)
#pragma unroll
            for (int nt = 0; nt < 4; nt++)
#pragma unroll
                for (int j = 0; j < 4; j++)
                    P[mt * 16 + nt * 4 + j] = cP * acc[mt][nt][j] + cL;
    }
    __syncthreads();   // Q/V tile reads done

    // ---- load W bf16 hi/lo ----
    {
        const uint32_t* w1g = (const uint32_t*)gW1 + b * 8192;
        const uint32_t* w2g = (const uint32_t*)gW2 + b * 8192;
        for (int idx = t; idx < 8192; idx += 512) {
            int row = idx >> 6, cw = idx & 63;
            *(uint32_t*)(w1B + row * S136 + cw * 2) = w1g[row * 64 + cw];
            *(uint32_t*)(w2B + row * S136 + cw * 2) = w2g[row * 64 + cw];
        }
    }

    float xu[32];
#pragma unroll
    for (int e = 0; e < 32; e++) xu[e] = 0.0f;

    // initial rhs (it=0): z=u=0 -> (0-0)-P, into buf0
#pragma unroll
    for (int mt = 0; mt < 2; mt++) {
        int ra = rA + 16 * mt, rb = ra + 8;
#pragma unroll
        for (int nt = 0; nt < 4; nt++) {
            int e = mt * 16 + nt * 4;
            int c = n0 + nt * 8 + 2 * tig;
            uint32_t hi, lo;
            split2((0.0f - 0.0f) - P[e], (0.0f - 0.0f) - P[e + 1], hi, lo);
            *(uint32_t*)(rh0 + ra * S136 + c) = hi;
            *(uint32_t*)(rl0 + ra * S136 + c) = lo;
            split2((0.0f - 0.0f) - P[e + 2], (0.0f - 0.0f) - P[e + 3], hi, lo);
            *(uint32_t*)(rh0 + rb * S136 + c) = hi;
            *(uint32_t*)(rl0 + rb * S136 + c) = lo;
        }
    }
    __syncthreads();   // covers W load + initial rhs

    // ---- 50 ADMM iterations: GEMM(buf p) -> fused pointwise+store(buf 1-p) -> bar ----
    for (int it = 0; it < ITERS; it++) {
        const __nv_bfloat16* rhR = (it & 1) ? rh1 : rh0;
        const __nv_bfloat16* rlR = (it & 1) ? rl1 : rl0;
        __nv_bfloat16* rhW = (it & 1) ? rh0 : rh1;
        __nv_bfloat16* rlW = (it & 1) ? rl0 : rl1;

        float acc[2][4][4];
#pragma unroll
        for (int mt = 0; mt < 2; mt++)
#pragma unroll
            for (int nt = 0; nt < 4; nt++)
#pragma unroll
                for (int j = 0; j < 4; j++) acc[mt][nt][j] = 0.0f;
        gemm3s(acc, rhR, rlR, w1B, w2B, rA, n0, tig, gid);

        // fused pointwise update + next-rhs store (same per-element expressions)
#pragma unroll
        for (int mt = 0; mt < 2; mt++) {
            int ra = rA + 16 * mt, rb = ra + 8;
#pragma unroll
            for (int nt = 0; nt < 4; nt++) {
                int e = mt * 16 + nt * 4;
                int c = n0 + nt * 8 + 2 * tig;
                float r4[4];
#pragma unroll
                for (int j = 0; j < 4; j++) {
                    int ee = e + j;
                    float zd = fminf(fmaxf(xu[ee], 0.0f), 1.0f);
                    float ud = xu[ee] - zd;
                    float rhs = (zd - ud) - P[ee];
                    float x = rhs + acc[mt][nt][j];
                    xu[ee] = x + ud;
                    float zd2 = fminf(fmaxf(xu[ee], 0.0f), 1.0f);
                    float ud2 = xu[ee] - zd2;
                    r4[j] = (zd2 - ud2) - P[ee];
                }
                uint32_t hi, lo;
                split2(r4[0], r4[1], hi, lo);
                *(uint32_t*)(rhW + ra * S136 + c) = hi;
                *(uint32_t*)(rlW + ra * S136 + c) = lo;
                split2(r4[2], r4[3], hi, lo);
                *(uint32_t*)(rhW + rb * S136 + c) = hi;
                *(uint32_t*)(rlW + rb * S136 + c) = lo;
            }
        }
        barg128(1 + g);
    }

    // ---- epilogue: counts, coeffs, out = coeff * (V/128) ----
    float z[32];
#pragma unroll
    for (int e = 0; e < 32; e++) z[e] = fminf(fmaxf(xu[e], 0.0f), 1.0f);
#pragma unroll
    for (int mt = 0; mt < 2; mt++) {
        int ra = rA + 16 * mt, rb = ra + 8;
        float c0s = 0.0f, c1s = 0.0f;
#pragma unroll
        for (int nt = 0; nt < 4; nt++) {
            int e = mt * 16 + nt * 4;
            c0s += ((z[e]     > 0.5f) ? 1.0f : 0.0f) + ((z[e + 1] > 0.5f) ? 1.0f : 0.0f);
            c1s += ((z[e + 2] > 0.5f) ? 1.0f : 0.0f) + ((z[e + 3] > 0.5f) ? 1.0f : 0.0f);
        }
        sCnt[ra * 16 + wg2 * 4 + tig] = c0s;
        sCnt[rb * 16 + wg2 * 4 + tig] = c1s;
    }
    barg128(1 + g);
    float inv[2][2];
#pragma unroll
    for (int mt = 0; mt < 2; mt++) {
        int ra = rA + 16 * mt, rb = ra + 8;
        float s0 = 0.0f, s1 = 0.0f;
#pragma unroll
        for (int k = 0; k < 16; k++) { s0 += sCnt[ra * 16 + k]; s1 += sCnt[rb * 16 + k]; }
        inv[mt][0] = 1.0f / (128.0f * (s0 + 1e-10f));
        inv[mt][1] = 1.0f / (128.0f * (s1 + 1e-10f));
    }
#pragma unroll
    for (int mt = 0; mt < 2; mt++) {
        int ra = rA + 16 * mt, rb = ra + 8;
#pragma unroll
        for (int nt = 0; nt < 4; nt++) {
            int e = mt * 16 + nt * 4;
            int c = n0 + nt * 8 + 2 * tig;
            uint32_t hi, lo;
            split2((z[e]     > 0.5f) ? inv[mt][0] : 0.0f,
                   (z[e + 1] > 0.5f) ? inv[mt][0] : 0.0f, hi, lo);
            *(uint32_t*)(rh0 + ra * S136 + c) = hi;
            *(uint32_t*)(rl0 + ra * S136 + c) = lo;
            split2((z[e + 2] > 0.5f) ? inv[mt][1] : 0.0f,
                   (z[e + 3] > 0.5f) ? inv[mt][1] : 0.0f, hi, lo);
            *(uint32_t*)(rh0 + rb * S136 + c) = hi;
            *(uint32_t*)(rl0 + rb * S136 + c) = lo;
        }
    }
    __syncthreads();   // last-iter W reads + coeff writes done (all groups)
    for (int idx = t; idx < 16384; idx += 512) {
        int m = idx >> 7, d = idx & 127;
        float f = Vb[idx];
        __nv_bfloat16 h = __float2bfloat16(f);
        w1B[d * S136 + m] = h;
        w2B[d * S136 + m] = __float2bfloat16(f - __bfloat162float(h));
    }
    __syncthreads();

    {
        float acc[2][4][4];
#pragma unroll
        for (int mt = 0; mt < 2; mt++)
#pragma unroll
            for (int nt = 0; nt < 4; nt++)
#pragma unroll
                for (int j = 0; j < 4; j++) acc[mt][nt][j] = 0.0f;
        gemm3s(acc, rh0, rl0, w1B, w2B, rA, n0, tig, gid);
        float* ob = gOut + (size_t)(b * NN + row0) * 128;
#pragma unroll
        for (int mt = 0; mt < 2; mt++) {
            int ra = rA + 16 * mt, rb = ra + 8;
#pragma unroll
            for (int nt = 0; nt < 4; nt++) {
                int c = n0 + nt * 8 + 2 * tig;
                *(float2*)(ob + ra * 128 + c) = make_float2(acc[mt][nt][0], acc[mt][nt][1]);
                *(float2*)(ob + rb * 128 + c) = make_float2(acc[mt][nt][2], acc[mt][nt][3]);
            }
        }
    }
}

// ============================================================================

extern "C" void kernel_launch(void* const* d_in, const int* in_sizes, int n_in,
                              void* d_out, int out_size) {
    const float* gQ = (const float*)d_in[0];
    const float* gV = (const float*)d_in[1];
    if (n_in >= 2 && in_sizes[0] == BB * 128 * 128 && in_sizes[1] == BB * NN * 128) {
        gV = (const float*)d_in[0];
        gQ = (const float*)d_in[1];
    }
    float* out = (float*)d_out;

    const int SMEM_E   = 128 * 132 * 4;                // 67584
    const int SMEM_MM1 = (8 * 129 + 128 * 128) * 4;    // 69664
    const int SMEM_MM2 = (16 * 129 + 128 * 128) * 4;   // 73792

    cudaFuncSetAttribute(kE,   cudaFuncAttributeMaxDynamicSharedMemorySize, SMEM_E);
    cudaFuncSetAttribute(kMM1, cudaFuncAttributeMaxDynamicSharedMemorySize, SMEM_MM1);
    cudaFuncSetAttribute(kMM2, cudaFuncAttributeMaxDynamicSharedMemorySize, SMEM_MM2);
    cudaFuncSetAttribute(k_admm, cudaFuncAttributeMaxDynamicSharedMemorySize, SMEM_ADMM);

    kE<<<64, 256, SMEM_E>>>(gV);
    kMM1<<<128, 256, SMEM_MM1>>>();       // E2 = E*E ; S = I - E + E2
    kMM2<<<128, 256, SMEM_MM2>>>();       // W = E2*S - E -> bf16 hi/lo
    k_admm<<<BB * (NN / 128), 512, SMEM_ADMM>>>(gQ, gV, out);
}